// round 11
// baseline (speedup 1.0000x reference)
#include <cuda_runtime.h>
#include <cstdint>

#define TT 100
#define BB 1024
#define NIN 784
#define NHID 1000
#define NOUT 10

#define KC 320          // Eigen gebp k-panel (validated R5)
#define NCHUNK 4
#define TC (TT / NCHUNK)   // 25 timesteps per pipeline chunk

// cur1 scratch [T, B, NHID] = 409.6 MB
__device__ float g_cur1[(size_t)TT * BB * NHID];
// LIF carry state between chunks
__device__ float    g_mem1s[BB][1024];
__device__ uint32_t g_rst1s[BB][128];
__device__ float    g_mem2s[BB][NOUT];
__device__ float    g_rst2s[BB][NOUT];

typedef unsigned long long u64;

__device__ __forceinline__ u64 fma2(u64 a, u64 b, u64 c) {
    u64 d;
    asm("fma.rn.f32x2 %0, %1, %2, %3;" : "=l"(d) : "l"(a), "l"(b), "l"(c));
    return d;
}
__device__ __forceinline__ u64 add2(u64 a, u64 b) {
    u64 d;
    asm("add.rn.f32x2 %0, %1, %2;" : "=l"(d) : "l"(a), "l"(b));
    return d;
}
__device__ __forceinline__ void unpack2(u64 v, float& x, float& y) {
    asm("mov.b64 {%0,%1}, %2;" : "=f"(x), "=f"(y) : "l"(v));
}

// ---------------------------------------------------------------------------
// Kernel A: cur1[m,n] = ((P0+P1)+P2) + b1[n]  (kc=320 chain association).
// FFMA2 (lanewise == scalar __fmaf_rn). BK=16: one sync per 16 k.
// Dup-A smem so packed multipliers load via LDS.128.
// ---------------------------------------------------------------------------
#define BM 128
#define BN 128
#define BK 16
#define PADA 260
#define PADR 132
#define NITER (NIN / BK)      // 49; panel ends after it 19 (k=320), 39 (k=640), 48

__global__ void __launch_bounds__(256, 1) gemm_cur1_kernel(
    const float* __restrict__ X,   // [M=T*B, K]
    const float* __restrict__ W1,  // [NHID, K]
    const float* __restrict__ b1,  // [NHID]
    int m_base)                    // chunk row offset
{
    __shared__ float As2[2][BK][PADA];   // duplicated pairs
    __shared__ float Bs[2][BK][PADR];

    const int tid = threadIdx.x;
    const int tx = tid & 15;
    const int ty = tid >> 4;
    const int m0 = m_base + blockIdx.y * BM;
    const int n0 = blockIdx.x * BN;

    const int lrow = tid >> 1;           // 0..127
    const int lcol = (tid & 1) * 8;      // 0 or 8

    const float* Aptr = X  + (size_t)(m0 + lrow) * NIN + lcol;
    const float* Bptr = W1 + (size_t)(n0 + lrow) * NIN + lcol;
    const bool bvalid = (n0 + lrow) < NHID;

    u64 c2[8][4];
#pragma unroll
    for (int i = 0; i < 8; ++i)
#pragma unroll
        for (int j = 0; j < 4; ++j) c2[i][j] = 0ull;
    u64 pa2[8][4];

    // prologue stage 0
    {
        float4 a0 = *(const float4*)(Aptr);
        float4 a1 = *(const float4*)(Aptr + 4);
        float4 bv0 = make_float4(0, 0, 0, 0), bv1 = make_float4(0, 0, 0, 0);
        if (bvalid) { bv0 = *(const float4*)(Bptr); bv1 = *(const float4*)(Bptr + 4); }
        const float a[8] = {a0.x, a0.y, a0.z, a0.w, a1.x, a1.y, a1.z, a1.w};
        const float bb[8] = {bv0.x, bv0.y, bv0.z, bv0.w, bv1.x, bv1.y, bv1.z, bv1.w};
#pragma unroll
        for (int q = 0; q < 8; ++q) {
            *(float2*)&As2[0][lcol + q][2 * lrow] = make_float2(a[q], a[q]);
            Bs[0][lcol + q][lrow] = bb[q];
        }
    }
    __syncthreads();

    int buf = 0;
#pragma unroll 1
    for (int it = 0; it < NITER; ++it) {
        if (it == 0 || it == 20 || it == 40) {
#pragma unroll
            for (int i = 0; i < 8; ++i)
#pragma unroll
                for (int j = 0; j < 4; ++j) pa2[i][j] = 0ull;
        }

        const bool notlast = (it < NITER - 1);
        float4 na0 = make_float4(0, 0, 0, 0), na1 = na0, nb0 = na0, nb1 = na0;
        if (notlast) {
            na0 = *(const float4*)(Aptr + (it + 1) * BK);
            na1 = *(const float4*)(Aptr + (it + 1) * BK + 4);
            if (bvalid) {
                nb0 = *(const float4*)(Bptr + (it + 1) * BK);
                nb1 = *(const float4*)(Bptr + (it + 1) * BK + 4);
            }
        }

#pragma unroll
        for (int k = 0; k < BK; ++k) {
            u64 a2[8], b2[4];
#pragma unroll
            for (int q = 0; q < 4; ++q) {
                const float4 v = *(const float4*)(&As2[buf][k][ty * 16 + q * 4]);
                a2[2 * q]     = *(const u64*)&v.x;
                a2[2 * q + 1] = *(const u64*)&v.z;
            }
            {
                const float4 v0 = *(const float4*)(&Bs[buf][k][tx * 8]);
                const float4 v1 = *(const float4*)(&Bs[buf][k][tx * 8 + 4]);
                b2[0] = *(const u64*)&v0.x;
                b2[1] = *(const u64*)&v0.z;
                b2[2] = *(const u64*)&v1.x;
                b2[3] = *(const u64*)&v1.z;
            }
#pragma unroll
            for (int i = 0; i < 8; ++i)
#pragma unroll
                for (int j = 0; j < 4; ++j)
                    pa2[i][j] = fma2(a2[i], b2[j], pa2[i][j]);
        }

        if (it == 19 || it == 39 || it == NITER - 1) {
#pragma unroll
            for (int i = 0; i < 8; ++i)
#pragma unroll
                for (int j = 0; j < 4; ++j) c2[i][j] = add2(c2[i][j], pa2[i][j]);
        }

        if (notlast) {
            const int nb = buf ^ 1;
            const float a[8] = {na0.x, na0.y, na0.z, na0.w, na1.x, na1.y, na1.z, na1.w};
            const float bb[8] = {nb0.x, nb0.y, nb0.z, nb0.w, nb1.x, nb1.y, nb1.z, nb1.w};
#pragma unroll
            for (int q = 0; q < 8; ++q) {
                *(float2*)&As2[nb][lcol + q][2 * lrow] = make_float2(a[q], a[q]);
                Bs[nb][lcol + q][lrow] = bb[q];
            }
            __syncthreads();
            buf = nb;
        }
    }

#pragma unroll
    for (int i = 0; i < 8; ++i) {
        const size_t row = (size_t)(m0 + ty * 8 + i) * NHID;
#pragma unroll
        for (int j = 0; j < 4; ++j) {
            float lo, hi;
            unpack2(c2[i][j], lo, hi);
            const int n = n0 + tx * 8 + 2 * j;
            if (n < NHID)     g_cur1[row + n]     = __fadd_rn(lo, b1[n]);
            if (n + 1 < NHID) g_cur1[row + n + 1] = __fadd_rn(hi, b1[n + 1]);
        }
    }
}

// ---------------------------------------------------------------------------
// Kernel B: one chunk of TC timesteps; state carried via device globals.
// Parallel kc=320 panels on lanes o/o+10/o+20 (bitwise-validated R9).
// ---------------------------------------------------------------------------
#define W2P 1001

__global__ void __launch_bounds__(128) lif_chunk_kernel(
    const float* __restrict__ W2, const float* __restrict__ b2,
    float* __restrict__ out, int t0)
{
    const int b    = blockIdx.x;
    const int tid  = threadIdx.x;
    const int warp = tid >> 5, lane = tid & 31;

    __shared__ float    W2s[NOUT * W2P];
    __shared__ uint32_t masks[2][32];
    __shared__ uint16_t list[2][1024];

    for (int i = tid; i < NOUT * NHID; i += 128) {
        const int o = i / NHID, h = i - o * NHID;
        W2s[o * W2P + h] = W2[i];
    }

    float mem1[8];
    uint32_t rstb;
    float mem2 = 0.f, rst2 = 0.f, b2v = 0.f;

    if (t0 == 0) {
#pragma unroll
        for (int i = 0; i < 8; ++i) mem1[i] = 0.f;
        rstb = 0;
    } else {
#pragma unroll
        for (int i = 0; i < 8; ++i) mem1[i] = g_mem1s[b][i * 128 + tid];
        rstb = g_rst1s[b][tid];
        if (warp == 0 && lane < NOUT) {
            mem2 = g_mem2s[b][lane];
            rst2 = g_rst2s[b][lane];
        }
    }
    if (tid < NOUT) b2v = b2[tid];

    const float* cr0 = g_cur1 + (size_t)b * NHID;
    const size_t tstride = (size_t)BB * NHID;

    float cv[8];
#pragma unroll
    for (int i = 0; i < 8; ++i) {
        const int h = i * 128 + tid;
        cv[i] = (h < NHID) ? __ldg(cr0 + (size_t)t0 * tstride + h) : 0.f;
    }
    __syncthreads();

    int par = 0;
    for (int t = t0; t < t0 + TC; ++t) {
        uint32_t nrst = 0;
#pragma unroll
        for (int i = 0; i < 8; ++i) {
            const int h = i * 128 + tid;
            const float rstv = ((rstb >> i) & 1u) ? 1.f : 0.f;
            const float m = __fsub_rn(__fadd_rn(__fmul_rn(0.9f, mem1[i]), cv[i]), rstv);
            mem1[i] = m;
            const bool s = (m > 1.0f) && (h < NHID);
            const uint32_t bal = __ballot_sync(0xffffffffu, s);
            if (lane == 0) masks[par][i * 4 + warp] = bal;
            if (s) nrst |= (1u << i);
        }
        rstb = nrst;

        float nvv[8];
#pragma unroll
        for (int i = 0; i < 8; ++i) nvv[i] = 0.f;
        if (t + 1 < t0 + TC) {
            const float* crn = cr0 + (size_t)(t + 1) * tstride;
#pragma unroll
            for (int i = 0; i < 8; ++i) {
                const int h = i * 128 + tid;
                if (h < NHID) nvv[i] = __ldg(crn + h);
            }
        }
        __syncthreads();

        if (warp == 0) {
            const uint32_t mw = masks[par][lane];
            const int cnt = __popc(mw);
            int inc = cnt;
#pragma unroll
            for (int d = 1; d < 32; d <<= 1) {
                const int v = __shfl_up_sync(0xffffffffu, inc, d);
                if (lane >= d) inc += v;
            }
            const int excl = inc - cnt;
            const int tot = __shfl_sync(0xffffffffu, inc, 31);
            const int p1  = __shfl_sync(0xffffffffu, excl, 10);
            const int p2  = __shfl_sync(0xffffffffu, excl, 20);
            {
                uint32_t m2w = mw;
                int o = excl;
                const int base = lane * 32;
                while (m2w) {
                    const int bi = __ffs(m2w) - 1;
                    list[par][o++] = (uint16_t)(base + bi);
                    m2w &= m2w - 1;
                }
            }
            __syncwarp();

            const int p = (lane >= 20) ? 2 : ((lane >= 10) ? 1 : 0);
            const int o = lane - p * 10;
            float pacc = 0.f;
            if (lane < 30) {
                const int s0 = (p == 0) ? 0  : ((p == 1) ? p1 : p2);
                const int e0 = (p == 0) ? p1 : ((p == 1) ? p2 : tot);
                const float* wrow = &W2s[o * W2P];
                const uint16_t* L = list[par];
#pragma unroll 4
                for (int ii = s0; ii < e0; ++ii)
                    pacc = __fadd_rn(pacc, wrow[L[ii]]);
            }
            const float v1 = __shfl_sync(0xffffffffu, pacc, (lane + 10) & 31);
            const float v2 = __shfl_sync(0xffffffffu, pacc, (lane + 20) & 31);

            if (lane < NOUT) {
                const float acc = __fadd_rn(__fadd_rn(pacc, v1), v2);
                const float c2v = __fadd_rn(acc, b2v);
                const float m2 = __fsub_rn(__fadd_rn(__fmul_rn(0.9f, mem2), c2v), rst2);
                const float s2 = (m2 > 1.0f) ? 1.0f : 0.0f;
                mem2 = m2;
                rst2 = s2;
                const size_t idx = ((size_t)t * BB + b) * NOUT + lane;
                out[idx] = s2;
                out[(size_t)TT * BB * NOUT + idx] = m2;
            }
        }

        par ^= 1;
#pragma unroll
        for (int i = 0; i < 8; ++i) cv[i] = nvv[i];
    }

    // store carry state
#pragma unroll
    for (int i = 0; i < 8; ++i) g_mem1s[b][i * 128 + tid] = mem1[i];
    g_rst1s[b][tid] = rstb;
    if (warp == 0 && lane < NOUT) {
        g_mem2s[b][lane] = mem2;
        g_rst2s[b][lane] = rst2;
    }
}

// ---------------------------------------------------------------------------
extern "C" void kernel_launch(void* const* d_in, const int* in_sizes, int n_in,
                              void* d_out, int out_size)
{
    const float* x  = (const float*)d_in[0];
    const float* W1 = (const float*)d_in[1];
    const float* b1 = (const float*)d_in[2];
    const float* W2 = (const float*)d_in[3];
    const float* b2 = (const float*)d_in[4];
    float* out = (float*)d_out;

    static cudaStream_t s2 = nullptr;
    static cudaEvent_t evFork, evJoin, evG[NCHUNK];
    if (s2 == nullptr) {   // one-time infra setup (outside capture: the
        cudaStreamCreateWithFlags(&s2, cudaStreamNonBlocking);   // correctness
        cudaEventCreateWithFlags(&evFork, cudaEventDisableTiming);  // run comes
        cudaEventCreateWithFlags(&evJoin, cudaEventDisableTiming);  // first)
        for (int c = 0; c < NCHUNK; ++c)
            cudaEventCreateWithFlags(&evG[c], cudaEventDisableTiming);
    }

    cudaEventRecord(evFork, 0);
    cudaStreamWaitEvent(s2, evFork, 0);

    dim3 grid((NHID + BN - 1) / BN, (TC * BB) / BM);   // (8, 200) per chunk
    for (int c = 0; c < NCHUNK; ++c) {
        gemm_cur1_kernel<<<grid, 256>>>(x, W1, b1, c * TC * BB);
        cudaEventRecord(evG[c], 0);
        cudaStreamWaitEvent(s2, evG[c], 0);
        lif_chunk_kernel<<<BB, 128, 0, s2>>>(W2, b2, out, c * TC);
    }

    cudaEventRecord(evJoin, s2);
    cudaStreamWaitEvent(0, evJoin, 0);
}

// round 12
// speedup vs baseline: 1.1790x; 1.1790x over previous
#include <cuda_runtime.h>
#include <cstdint>

#define TT 100
#define BB 1024
#define NIN 784
#define NHID 1000
#define NOUT 10

#define KC 320             // Eigen gebp k-panel (validated R5)
#define NCHUNK 4
#define TC (TT / NCHUNK)   // 25 timesteps per pipeline chunk

// cur1 scratch [T, B, NHID] = 409.6 MB
__device__ float g_cur1[(size_t)TT * BB * NHID];
// LIF carry state between chunks
__device__ float    g_mem1s[BB][1024];
__device__ uint32_t g_rst1s[BB][128];
__device__ float    g_mem2s[BB][NOUT];
__device__ float    g_rst2s[BB][NOUT];

typedef unsigned long long u64;

__device__ __forceinline__ u64 fma2(u64 a, u64 b, u64 c) {
    u64 d;
    asm("fma.rn.f32x2 %0, %1, %2, %3;" : "=l"(d) : "l"(a), "l"(b), "l"(c));
    return d;
}
__device__ __forceinline__ u64 add2(u64 a, u64 b) {
    u64 d;
    asm("add.rn.f32x2 %0, %1, %2;" : "=l"(d) : "l"(a), "l"(b));
    return d;
}
__device__ __forceinline__ u64 dup2(float x) {
    u64 r;
    asm("mov.b64 %0, {%1,%1};" : "=l"(r) : "f"(x));
    return r;
}
__device__ __forceinline__ void unpack2(u64 v, float& x, float& y) {
    asm("mov.b64 {%0,%1}, %2;" : "=f"(x), "=f"(y) : "l"(v));
}

// ---------------------------------------------------------------------------
// Kernel A: cur1[m,n] = ((P0+P1)+P2) + b1[n]  (kc=320 chain association).
// FFMA2 with accumulator pairs along M: a-pairs load natively from plain
// m-contiguous smem (LDS.128), b scalars broadcast-packed in registers.
// Per k-step/thread: 4x LDS.128 + 32 FFMA2 + 8 movs -> LDS & FMA balanced.
// ---------------------------------------------------------------------------
#define BM 128
#define BN 128
#define BK 16
#define PADR 132              // row stride (floats): 528B, 16B-aligned
#define NITER (NIN / BK)      // 49; panel ends after it 19 (k=320), 39 (k=640)

__global__ void __launch_bounds__(256, 1) gemm_cur1_kernel(
    const float* __restrict__ X,   // [M=T*B, K]
    const float* __restrict__ W1,  // [NHID, K]
    const float* __restrict__ b1,  // [NHID]
    int m_base)
{
    __shared__ float As[2][BK][PADR];
    __shared__ float Bs[2][BK][PADR];

    const int tid = threadIdx.x;
    const int tx = tid & 15;        // n-group
    const int ty = tid >> 4;        // m-group
    const int m0 = m_base + blockIdx.y * BM;
    const int n0 = blockIdx.x * BN;

    const int lrow = tid >> 1;           // 0..127
    const int lcol = (tid & 1) * 8;      // 0 or 8

    const float* Aptr = X  + (size_t)(m0 + lrow) * NIN + lcol;
    const float* Bptr = W1 + (size_t)(n0 + lrow) * NIN + lcol;
    const bool bvalid = (n0 + lrow) < NHID;

    // accumulators: pairs along m. c2[i][j] = (C[2i][j], C[2i+1][j])
    u64 c2[4][8], pa2[4][8];
#pragma unroll
    for (int i = 0; i < 4; ++i)
#pragma unroll
        for (int j = 0; j < 8; ++j) c2[i][j] = 0ull;

    // prologue stage 0
    {
        float4 a0 = *(const float4*)(Aptr);
        float4 a1 = *(const float4*)(Aptr + 4);
        float4 bv0 = make_float4(0, 0, 0, 0), bv1 = make_float4(0, 0, 0, 0);
        if (bvalid) { bv0 = *(const float4*)(Bptr); bv1 = *(const float4*)(Bptr + 4); }
        const float a[8] = {a0.x, a0.y, a0.z, a0.w, a1.x, a1.y, a1.z, a1.w};
        const float bb[8] = {bv0.x, bv0.y, bv0.z, bv0.w, bv1.x, bv1.y, bv1.z, bv1.w};
#pragma unroll
        for (int q = 0; q < 8; ++q) {
            As[0][lcol + q][lrow] = a[q];
            Bs[0][lcol + q][lrow] = bb[q];
        }
    }
    __syncthreads();

    int buf = 0;
#pragma unroll 1
    for (int it = 0; it < NITER; ++it) {
        if (it == 0 || it == 20 || it == 40) {
#pragma unroll
            for (int i = 0; i < 4; ++i)
#pragma unroll
                for (int j = 0; j < 8; ++j) pa2[i][j] = 0ull;
        }

        const bool notlast = (it < NITER - 1);
        float4 na0 = make_float4(0, 0, 0, 0), na1 = na0, nb0 = na0, nb1 = na0;
        if (notlast) {
            na0 = *(const float4*)(Aptr + (it + 1) * BK);
            na1 = *(const float4*)(Aptr + (it + 1) * BK + 4);
            if (bvalid) {
                nb0 = *(const float4*)(Bptr + (it + 1) * BK);
                nb1 = *(const float4*)(Bptr + (it + 1) * BK + 4);
            }
        }

#pragma unroll
        for (int k = 0; k < BK; ++k) {
            // a-pairs: natural 8B words from m-contiguous smem
            u64 a2[4];
            {
                const float4 v0 = *(const float4*)(&As[buf][k][ty * 8]);
                const float4 v1 = *(const float4*)(&As[buf][k][ty * 8 + 4]);
                a2[0] = *(const u64*)&v0.x;
                a2[1] = *(const u64*)&v0.z;
                a2[2] = *(const u64*)&v1.x;
                a2[3] = *(const u64*)&v1.z;
            }
            // b scalars -> broadcast pairs in registers
            u64 bd[8];
            {
                const float4 v0 = *(const float4*)(&Bs[buf][k][tx * 8]);
                const float4 v1 = *(const float4*)(&Bs[buf][k][tx * 8 + 4]);
                bd[0] = dup2(v0.x); bd[1] = dup2(v0.y);
                bd[2] = dup2(v0.z); bd[3] = dup2(v0.w);
                bd[4] = dup2(v1.x); bd[5] = dup2(v1.y);
                bd[6] = dup2(v1.z); bd[7] = dup2(v1.w);
            }
#pragma unroll
            for (int i = 0; i < 4; ++i)
#pragma unroll
                for (int j = 0; j < 8; ++j)
                    pa2[i][j] = fma2(a2[i], bd[j], pa2[i][j]);
        }

        if (it == 19 || it == 39 || it == NITER - 1) {
#pragma unroll
            for (int i = 0; i < 4; ++i)
#pragma unroll
                for (int j = 0; j < 8; ++j) c2[i][j] = add2(c2[i][j], pa2[i][j]);
        }

        if (notlast) {
            const int nb = buf ^ 1;
            const float a[8] = {na0.x, na0.y, na0.z, na0.w, na1.x, na1.y, na1.z, na1.w};
            const float bb[8] = {nb0.x, nb0.y, nb0.z, nb0.w, nb1.x, nb1.y, nb1.z, nb1.w};
#pragma unroll
            for (int q = 0; q < 8; ++q) {
                As[nb][lcol + q][lrow] = a[q];
                Bs[nb][lcol + q][lrow] = bb[q];
            }
            __syncthreads();
            buf = nb;
        }
    }

    // epilogue: c2[i][j] holds rows (2i, 2i+1) of column tx*8+j
#pragma unroll
    for (int i = 0; i < 4; ++i) {
        const size_t row0 = (size_t)(m0 + ty * 8 + 2 * i) * NHID;
        const size_t row1 = row0 + NHID;
#pragma unroll
        for (int j = 0; j < 8; ++j) {
            const int n = n0 + tx * 8 + j;
            if (n < NHID) {
                float lo, hi;
                unpack2(c2[i][j], lo, hi);
                const float bb = b1[n];
                g_cur1[row0 + n] = __fadd_rn(lo, bb);
                g_cur1[row1 + n] = __fadd_rn(hi, bb);
            }
        }
    }
}

// ---------------------------------------------------------------------------
// Kernel B: one chunk of TC timesteps; carry state in device globals.
// Parallel kc=320 panels on lanes o/o+10/o+20 (bitwise-validated).
// ---------------------------------------------------------------------------
#define W2P 1001

__global__ void __launch_bounds__(128) lif_chunk_kernel(
    const float* __restrict__ W2, const float* __restrict__ b2,
    float* __restrict__ out, int t0)
{
    const int b    = blockIdx.x;
    const int tid  = threadIdx.x;
    const int warp = tid >> 5, lane = tid & 31;

    __shared__ float    W2s[NOUT * W2P];
    __shared__ uint32_t masks[2][32];
    __shared__ uint16_t list[2][1024];

    for (int i = tid; i < NOUT * NHID; i += 128) {
        const int o = i / NHID, h = i - o * NHID;
        W2s[o * W2P + h] = W2[i];
    }

    float mem1[8];
    uint32_t rstb;
    float mem2 = 0.f, rst2 = 0.f, b2v = 0.f;

    if (t0 == 0) {
#pragma unroll
        for (int i = 0; i < 8; ++i) mem1[i] = 0.f;
        rstb = 0;
    } else {
#pragma unroll
        for (int i = 0; i < 8; ++i) mem1[i] = g_mem1s[b][i * 128 + tid];
        rstb = g_rst1s[b][tid];
        if (warp == 0 && lane < NOUT) {
            mem2 = g_mem2s[b][lane];
            rst2 = g_rst2s[b][lane];
        }
    }
    if (tid < NOUT) b2v = b2[tid];

    const float* cr0 = g_cur1 + (size_t)b * NHID;
    const size_t tstride = (size_t)BB * NHID;

    float cv[8];
#pragma unroll
    for (int i = 0; i < 8; ++i) {
        const int h = i * 128 + tid;
        cv[i] = (h < NHID) ? __ldg(cr0 + (size_t)t0 * tstride + h) : 0.f;
    }
    __syncthreads();

    int par = 0;
    for (int t = t0; t < t0 + TC; ++t) {
        uint32_t nrst = 0;
#pragma unroll
        for (int i = 0; i < 8; ++i) {
            const int h = i * 128 + tid;
            const float rstv = ((rstb >> i) & 1u) ? 1.f : 0.f;
            const float m = __fsub_rn(__fadd_rn(__fmul_rn(0.9f, mem1[i]), cv[i]), rstv);
            mem1[i] = m;
            const bool s = (m > 1.0f) && (h < NHID);
            const uint32_t bal = __ballot_sync(0xffffffffu, s);
            if (lane == 0) masks[par][i * 4 + warp] = bal;
            if (s) nrst |= (1u << i);
        }
        rstb = nrst;

        float nvv[8];
#pragma unroll
        for (int i = 0; i < 8; ++i) nvv[i] = 0.f;
        if (t + 1 < t0 + TC) {
            const float* crn = cr0 + (size_t)(t + 1) * tstride;
#pragma unroll
            for (int i = 0; i < 8; ++i) {
                const int h = i * 128 + tid;
                if (h < NHID) nvv[i] = __ldg(crn + h);
            }
        }
        __syncthreads();

        if (warp == 0) {
            const uint32_t mw = masks[par][lane];
            const int cnt = __popc(mw);
            int inc = cnt;
#pragma unroll
            for (int d = 1; d < 32; d <<= 1) {
                const int v = __shfl_up_sync(0xffffffffu, inc, d);
                if (lane >= d) inc += v;
            }
            const int excl = inc - cnt;
            const int tot = __shfl_sync(0xffffffffu, inc, 31);
            const int p1  = __shfl_sync(0xffffffffu, excl, 10);
            const int p2  = __shfl_sync(0xffffffffu, excl, 20);
            {
                uint32_t m2w = mw;
                int o = excl;
                const int base = lane * 32;
                while (m2w) {
                    const int bi = __ffs(m2w) - 1;
                    list[par][o++] = (uint16_t)(base + bi);
                    m2w &= m2w - 1;
                }
            }
            __syncwarp();

            const int p = (lane >= 20) ? 2 : ((lane >= 10) ? 1 : 0);
            const int o = lane - p * 10;
            float pacc = 0.f;
            if (lane < 30) {
                const int s0 = (p == 0) ? 0  : ((p == 1) ? p1 : p2);
                const int e0 = (p == 0) ? p1 : ((p == 1) ? p2 : tot);
                const float* wrow = &W2s[o * W2P];
                const uint16_t* L = list[par];
#pragma unroll 4
                for (int ii = s0; ii < e0; ++ii)
                    pacc = __fadd_rn(pacc, wrow[L[ii]]);
            }
            const float v1 = __shfl_sync(0xffffffffu, pacc, (lane + 10) & 31);
            const float v2 = __shfl_sync(0xffffffffu, pacc, (lane + 20) & 31);

            if (lane < NOUT) {
                const float acc = __fadd_rn(__fadd_rn(pacc, v1), v2);
                const float c2v = __fadd_rn(acc, b2v);
                const float m2 = __fsub_rn(__fadd_rn(__fmul_rn(0.9f, mem2), c2v), rst2);
                const float s2 = (m2 > 1.0f) ? 1.0f : 0.0f;
                mem2 = m2;
                rst2 = s2;
                const size_t idx = ((size_t)t * BB + b) * NOUT + lane;
                out[idx] = s2;
                out[(size_t)TT * BB * NOUT + idx] = m2;
            }
        }

        par ^= 1;
#pragma unroll
        for (int i = 0; i < 8; ++i) cv[i] = nvv[i];
    }

#pragma unroll
    for (int i = 0; i < 8; ++i) g_mem1s[b][i * 128 + tid] = mem1[i];
    g_rst1s[b][tid] = rstb;
    if (warp == 0 && lane < NOUT) {
        g_mem2s[b][lane] = mem2;
        g_rst2s[b][lane] = rst2;
    }
}

// ---------------------------------------------------------------------------
extern "C" void kernel_launch(void* const* d_in, const int* in_sizes, int n_in,
                              void* d_out, int out_size)
{
    const float* x  = (const float*)d_in[0];
    const float* W1 = (const float*)d_in[1];
    const float* b1 = (const float*)d_in[2];
    const float* W2 = (const float*)d_in[3];
    const float* b2 = (const float*)d_in[4];
    float* out = (float*)d_out;

    static cudaStream_t s2 = nullptr;
    static cudaEvent_t evFork, evJoin, evG[NCHUNK];
    if (s2 == nullptr) {   // one-time setup; correctness run precedes capture
        cudaStreamCreateWithFlags(&s2, cudaStreamNonBlocking);
        cudaEventCreateWithFlags(&evFork, cudaEventDisableTiming);
        cudaEventCreateWithFlags(&evJoin, cudaEventDisableTiming);
        for (int c = 0; c < NCHUNK; ++c)
            cudaEventCreateWithFlags(&evG[c], cudaEventDisableTiming);
    }

    cudaEventRecord(evFork, 0);
    cudaStreamWaitEvent(s2, evFork, 0);

    dim3 grid((NHID + BN - 1) / BN, (TC * BB) / BM);   // (8, 200) per chunk
    for (int c = 0; c < NCHUNK; ++c) {
        gemm_cur1_kernel<<<grid, 256>>>(x, W1, b1, c * TC * BB);
        cudaEventRecord(evG[c], 0);
        cudaStreamWaitEvent(s2, evG[c], 0);
        lif_chunk_kernel<<<BB, 128, 0, s2>>>(W2, b2, out, c * TC);
    }

    cudaEventRecord(evJoin, s2);
    cudaStreamWaitEvent(0, evJoin, 0);
}

// round 13
// speedup vs baseline: 1.2320x; 1.0449x over previous
#include <cuda_runtime.h>
#include <cstdint>

#define TT 100
#define BB 1024
#define NIN 784
#define NHID 1000
#define NOUT 10

#define KC 320             // Eigen gebp k-panel (validated R5)
#define NCHUNK 4
#define TC (TT / NCHUNK)

// cur1 scratch [T, B, NHID] = 409.6 MB
__device__ float g_cur1[(size_t)TT * BB * NHID];
// LIF carry state between chunks
__device__ float    g_mem1s[BB][1024];
__device__ uint32_t g_rst1s[BB][128];
__device__ float    g_mem2s[BB][NOUT];
__device__ float    g_rst2s[BB][NOUT];

typedef unsigned long long u64;

__device__ __forceinline__ u64 fma2(u64 a, u64 b, u64 c) {
    u64 d;
    asm("fma.rn.f32x2 %0, %1, %2, %3;" : "=l"(d) : "l"(a), "l"(b), "l"(c));
    return d;
}
__device__ __forceinline__ u64 add2(u64 a, u64 b) {
    u64 d;
    asm("add.rn.f32x2 %0, %1, %2;" : "=l"(d) : "l"(a), "l"(b));
    return d;
}
__device__ __forceinline__ u64 dup2(float x) {
    u64 r;
    asm("mov.b64 %0, {%1,%1};" : "=l"(r) : "f"(x));
    return r;
}
__device__ __forceinline__ void unpack2(u64 v, float& x, float& y) {
    asm("mov.b64 {%0,%1}, %2;" : "=f"(x), "=f"(y) : "l"(v));
}

// ---------------------------------------------------------------------------
// Kernel A: cur1[m,n] = ((P0+P1)+P2) + b1[n]  (kc=320 chain association).
// FFMA2, m-pair accumulators. Committed sums (c2) live in SMEM (touched only
// at 3 panel commits + epilogue) -> hot loop holds just pa2 (64 regs) ->
// 2 CTAs/SM (16 warps) for latency hiding.
// ---------------------------------------------------------------------------
#define BM 128
#define BN 128
#define BK 16
#define PADR 132
#define NITER (NIN / BK)      // 49; panel commits after it 19, 39, 48

#define SZ_AB   (2 * BK * PADR * 4)            // 16896 B each
#define OFF_BS  SZ_AB
#define OFF_C2  (2 * SZ_AB)                    // 33792
#define SMEM_GEMM (OFF_C2 + 32 * 256 * 8)      // + 65536 = 99328 B

__global__ void __launch_bounds__(256, 2) gemm_cur1_kernel(
    const float* __restrict__ X, const float* __restrict__ W1,
    const float* __restrict__ b1, int m_base)
{
    extern __shared__ char dsm[];
    float (*As)[BK][PADR] = (float (*)[BK][PADR])(dsm);
    float (*Bs)[BK][PADR] = (float (*)[BK][PADR])(dsm + OFF_BS);
    u64 (*c2s)[256]       = (u64 (*)[256])(dsm + OFF_C2);

    const int tid = threadIdx.x;
    const int tx = tid & 15;
    const int ty = tid >> 4;
    const int m0 = m_base + blockIdx.y * BM;
    const int n0 = blockIdx.x * BN;

    const int lrow = tid >> 1;
    const int lcol = (tid & 1) * 8;

    const float* Aptr = X  + (size_t)(m0 + lrow) * NIN + lcol;
    const float* Bptr = W1 + (size_t)(n0 + lrow) * NIN + lcol;
    const bool bvalid = (n0 + lrow) < NHID;

    u64 pa2[4][8];   // panel accumulators: (C[2i], C[2i+1]) of column j

    {
        float4 a0 = *(const float4*)(Aptr);
        float4 a1 = *(const float4*)(Aptr + 4);
        float4 bv0 = make_float4(0, 0, 0, 0), bv1 = make_float4(0, 0, 0, 0);
        if (bvalid) { bv0 = *(const float4*)(Bptr); bv1 = *(const float4*)(Bptr + 4); }
        const float a[8]  = {a0.x, a0.y, a0.z, a0.w, a1.x, a1.y, a1.z, a1.w};
        const float bb[8] = {bv0.x, bv0.y, bv0.z, bv0.w, bv1.x, bv1.y, bv1.z, bv1.w};
#pragma unroll
        for (int q = 0; q < 8; ++q) {
            As[0][lcol + q][lrow] = a[q];
            Bs[0][lcol + q][lrow] = bb[q];
        }
    }
    __syncthreads();

    int buf = 0;
#pragma unroll 1
    for (int it = 0; it < NITER; ++it) {
        if (it == 0 || it == 20 || it == 40) {
#pragma unroll
            for (int i = 0; i < 4; ++i)
#pragma unroll
                for (int j = 0; j < 8; ++j) pa2[i][j] = 0ull;
        }

        const bool notlast = (it < NITER - 1);
        float4 na0 = make_float4(0, 0, 0, 0), na1 = na0, nb0 = na0, nb1 = na0;
        if (notlast) {
            na0 = *(const float4*)(Aptr + (it + 1) * BK);
            na1 = *(const float4*)(Aptr + (it + 1) * BK + 4);
            if (bvalid) {
                nb0 = *(const float4*)(Bptr + (it + 1) * BK);
                nb1 = *(const float4*)(Bptr + (it + 1) * BK + 4);
            }
        }

#pragma unroll
        for (int k = 0; k < BK; ++k) {
            u64 a2[4];
            {
                const float4 v0 = *(const float4*)(&As[buf][k][ty * 8]);
                const float4 v1 = *(const float4*)(&As[buf][k][ty * 8 + 4]);
                a2[0] = *(const u64*)&v0.x;
                a2[1] = *(const u64*)&v0.z;
                a2[2] = *(const u64*)&v1.x;
                a2[3] = *(const u64*)&v1.z;
            }
            u64 bd[8];
            {
                const float4 v0 = *(const float4*)(&Bs[buf][k][tx * 8]);
                const float4 v1 = *(const float4*)(&Bs[buf][k][tx * 8 + 4]);
                bd[0] = dup2(v0.x); bd[1] = dup2(v0.y);
                bd[2] = dup2(v0.z); bd[3] = dup2(v0.w);
                bd[4] = dup2(v1.x); bd[5] = dup2(v1.y);
                bd[6] = dup2(v1.z); bd[7] = dup2(v1.w);
            }
#pragma unroll
            for (int i = 0; i < 4; ++i)
#pragma unroll
                for (int j = 0; j < 8; ++j)
                    pa2[i][j] = fma2(a2[i], bd[j], pa2[i][j]);
        }

        // Eigen panel commits (C += panel), committed value held in smem
        if (it == 19) {
#pragma unroll
            for (int i = 0; i < 4; ++i)
#pragma unroll
                for (int j = 0; j < 8; ++j) c2s[i * 8 + j][tid] = pa2[i][j];
        } else if (it == 39 || it == NITER - 1) {
#pragma unroll
            for (int i = 0; i < 4; ++i)
#pragma unroll
                for (int j = 0; j < 8; ++j)
                    c2s[i * 8 + j][tid] = add2(c2s[i * 8 + j][tid], pa2[i][j]);
        }

        if (notlast) {
            const int nb = buf ^ 1;
            const float a[8]  = {na0.x, na0.y, na0.z, na0.w, na1.x, na1.y, na1.z, na1.w};
            const float bb[8] = {nb0.x, nb0.y, nb0.z, nb0.w, nb1.x, nb1.y, nb1.z, nb1.w};
#pragma unroll
            for (int q = 0; q < 8; ++q) {
                As[nb][lcol + q][lrow] = a[q];
                Bs[nb][lcol + q][lrow] = bb[q];
            }
            __syncthreads();
            buf = nb;
        }
    }

#pragma unroll
    for (int i = 0; i < 4; ++i) {
        const size_t row0 = (size_t)(m0 + ty * 8 + 2 * i) * NHID;
        const size_t row1 = row0 + NHID;
#pragma unroll
        for (int j = 0; j < 8; ++j) {
            const int n = n0 + tx * 8 + j;
            if (n < NHID) {
                float lo, hi;
                unpack2(c2s[i * 8 + j][tid], lo, hi);
                const float bb = b1[n];
                g_cur1[row0 + n] = __fadd_rn(lo, bb);
                g_cur1[row1 + n] = __fadd_rn(hi, bb);
            }
        }
    }
}

// ---------------------------------------------------------------------------
// Kernel B (unchanged, bitwise-validated): chunked LIF recurrence.
// ---------------------------------------------------------------------------
#define W2P 1001

__global__ void __launch_bounds__(128) lif_chunk_kernel(
    const float* __restrict__ W2, const float* __restrict__ b2,
    float* __restrict__ out, int t0)
{
    const int b    = blockIdx.x;
    const int tid  = threadIdx.x;
    const int warp = tid >> 5, lane = tid & 31;

    __shared__ float    W2s[NOUT * W2P];
    __shared__ uint32_t masks[2][32];
    __shared__ uint16_t list[2][1024];

    for (int i = tid; i < NOUT * NHID; i += 128) {
        const int o = i / NHID, h = i - o * NHID;
        W2s[o * W2P + h] = W2[i];
    }

    float mem1[8];
    uint32_t rstb;
    float mem2 = 0.f, rst2 = 0.f, b2v = 0.f;

    if (t0 == 0) {
#pragma unroll
        for (int i = 0; i < 8; ++i) mem1[i] = 0.f;
        rstb = 0;
    } else {
#pragma unroll
        for (int i = 0; i < 8; ++i) mem1[i] = g_mem1s[b][i * 128 + tid];
        rstb = g_rst1s[b][tid];
        if (warp == 0 && lane < NOUT) {
            mem2 = g_mem2s[b][lane];
            rst2 = g_rst2s[b][lane];
        }
    }
    if (tid < NOUT) b2v = b2[tid];

    const float* cr0 = g_cur1 + (size_t)b * NHID;
    const size_t tstride = (size_t)BB * NHID;

    float cv[8];
#pragma unroll
    for (int i = 0; i < 8; ++i) {
        const int h = i * 128 + tid;
        cv[i] = (h < NHID) ? __ldg(cr0 + (size_t)t0 * tstride + h) : 0.f;
    }
    __syncthreads();

    int par = 0;
    for (int t = t0; t < t0 + TC; ++t) {
        uint32_t nrst = 0;
#pragma unroll
        for (int i = 0; i < 8; ++i) {
            const int h = i * 128 + tid;
            const float rstv = ((rstb >> i) & 1u) ? 1.f : 0.f;
            const float m = __fsub_rn(__fadd_rn(__fmul_rn(0.9f, mem1[i]), cv[i]), rstv);
            mem1[i] = m;
            const bool s = (m > 1.0f) && (h < NHID);
            const uint32_t bal = __ballot_sync(0xffffffffu, s);
            if (lane == 0) masks[par][i * 4 + warp] = bal;
            if (s) nrst |= (1u << i);
        }
        rstb = nrst;

        float nvv[8];
#pragma unroll
        for (int i = 0; i < 8; ++i) nvv[i] = 0.f;
        if (t + 1 < t0 + TC) {
            const float* crn = cr0 + (size_t)(t + 1) * tstride;
#pragma unroll
            for (int i = 0; i < 8; ++i) {
                const int h = i * 128 + tid;
                if (h < NHID) nvv[i] = __ldg(crn + h);
            }
        }
        __syncthreads();

        if (warp == 0) {
            const uint32_t mw = masks[par][lane];
            const int cnt = __popc(mw);
            int inc = cnt;
#pragma unroll
            for (int d = 1; d < 32; d <<= 1) {
                const int v = __shfl_up_sync(0xffffffffu, inc, d);
                if (lane >= d) inc += v;
            }
            const int excl = inc - cnt;
            const int tot = __shfl_sync(0xffffffffu, inc, 31);
            const int p1  = __shfl_sync(0xffffffffu, excl, 10);
            const int p2  = __shfl_sync(0xffffffffu, excl, 20);
            {
                uint32_t m2w = mw;
                int o = excl;
                const int base = lane * 32;
                while (m2w) {
                    const int bi = __ffs(m2w) - 1;
                    list[par][o++] = (uint16_t)(base + bi);
                    m2w &= m2w - 1;
                }
            }
            __syncwarp();

            const int p = (lane >= 20) ? 2 : ((lane >= 10) ? 1 : 0);
            const int o = lane - p * 10;
            float pacc = 0.f;
            if (lane < 30) {
                const int s0 = (p == 0) ? 0  : ((p == 1) ? p1 : p2);
                const int e0 = (p == 0) ? p1 : ((p == 1) ? p2 : tot);
                const float* wrow = &W2s[o * W2P];
                const uint16_t* L = list[par];
#pragma unroll 4
                for (int ii = s0; ii < e0; ++ii)
                    pacc = __fadd_rn(pacc, wrow[L[ii]]);
            }
            const float v1 = __shfl_sync(0xffffffffu, pacc, (lane + 10) & 31);
            const float v2 = __shfl_sync(0xffffffffu, pacc, (lane + 20) & 31);

            if (lane < NOUT) {
                const float acc = __fadd_rn(__fadd_rn(pacc, v1), v2);
                const float c2v = __fadd_rn(acc, b2v);
                const float m2 = __fsub_rn(__fadd_rn(__fmul_rn(0.9f, mem2), c2v), rst2);
                const float s2 = (m2 > 1.0f) ? 1.0f : 0.0f;
                mem2 = m2;
                rst2 = s2;
                const size_t idx = ((size_t)t * BB + b) * NOUT + lane;
                out[idx] = s2;
                out[(size_t)TT * BB * NOUT + idx] = m2;
            }
        }

        par ^= 1;
#pragma unroll
        for (int i = 0; i < 8; ++i) cv[i] = nvv[i];
    }

#pragma unroll
    for (int i = 0; i < 8; ++i) g_mem1s[b][i * 128 + tid] = mem1[i];
    g_rst1s[b][tid] = rstb;
    if (warp == 0 && lane < NOUT) {
        g_mem2s[b][lane] = mem2;
        g_rst2s[b][lane] = rst2;
    }
}

// ---------------------------------------------------------------------------
extern "C" void kernel_launch(void* const* d_in, const int* in_sizes, int n_in,
                              void* d_out, int out_size)
{
    const float* x  = (const float*)d_in[0];
    const float* W1 = (const float*)d_in[1];
    const float* b1 = (const float*)d_in[2];
    const float* W2 = (const float*)d_in[3];
    const float* b2 = (const float*)d_in[4];
    float* out = (float*)d_out;

    static cudaStream_t s2 = nullptr;
    static cudaEvent_t evFork, evJoin, evG[NCHUNK];
    if (s2 == nullptr) {   // one-time setup; correctness run precedes capture
        cudaStreamCreateWithFlags(&s2, cudaStreamNonBlocking);
        cudaEventCreateWithFlags(&evFork, cudaEventDisableTiming);
        cudaEventCreateWithFlags(&evJoin, cudaEventDisableTiming);
        for (int c = 0; c < NCHUNK; ++c)
            cudaEventCreateWithFlags(&evG[c], cudaEventDisableTiming);
        cudaFuncSetAttribute(gemm_cur1_kernel,
                             cudaFuncAttributeMaxDynamicSharedMemorySize,
                             SMEM_GEMM);
    }

    cudaEventRecord(evFork, 0);
    cudaStreamWaitEvent(s2, evFork, 0);

    dim3 grid((NHID + BN - 1) / BN, (TC * BB) / BM);   // (8, 200) per chunk
    for (int c = 0; c < NCHUNK; ++c) {
        gemm_cur1_kernel<<<grid, 256, SMEM_GEMM>>>(x, W1, b1, c * TC * BB);
        cudaEventRecord(evG[c], 0);
        cudaStreamWaitEvent(s2, evG[c], 0);
        lif_chunk_kernel<<<BB, 128, 0, s2>>>(W2, b2, out, c * TC);
    }

    cudaEventRecord(evJoin, s2);
    cudaStreamWaitEvent(0, evJoin, 0);
}

// round 14
// speedup vs baseline: 1.2979x; 1.0535x over previous
#include <cuda_runtime.h>
#include <cstdint>

#define TT 100
#define BB 1024
#define NIN 784
#define NHID 1000
#define NOUT 10

#define KC 320             // Eigen gebp k-panel (validated R5)
#define NCHUNK 4

// cur1 scratch [T, B, NHID] = 409.6 MB
__device__ float g_cur1[(size_t)TT * BB * NHID];
// LIF carry state between chunks
__device__ float    g_mem1s[BB][1024];
__device__ uint32_t g_rst1s[BB][128];
__device__ float    g_mem2s[BB][NOUT];
__device__ float    g_rst2s[BB][NOUT];

typedef unsigned long long u64;

__device__ __forceinline__ u64 fma2(u64 a, u64 b, u64 c) {
    u64 d;
    asm("fma.rn.f32x2 %0, %1, %2, %3;" : "=l"(d) : "l"(a), "l"(b), "l"(c));
    return d;
}
__device__ __forceinline__ u64 add2(u64 a, u64 b) {
    u64 d;
    asm("add.rn.f32x2 %0, %1, %2;" : "=l"(d) : "l"(a), "l"(b));
    return d;
}
__device__ __forceinline__ u64 dup2(float x) {
    u64 r;
    asm("mov.b64 %0, {%1,%1};" : "=l"(r) : "f"(x));
    return r;
}
__device__ __forceinline__ void unpack2(u64 v, float& x, float& y) {
    asm("mov.b64 {%0,%1}, %2;" : "=f"(x), "=f"(y) : "l"(v));
}

// ---------------------------------------------------------------------------
// Kernel A (R13 core, bitwise-validated): cur1[m,n] = ((P0+P1)+P2) + b1[n],
// kc=320 chain association, FFMA2 m-pair accumulators, committed sums in smem,
// 2 CTAs/SM.
// ---------------------------------------------------------------------------
#define BM 128
#define BN 128
#define BK 16
#define PADR 132
#define NITER (NIN / BK)      // 49; panel commits after it 19, 39, 48

#define SZ_AB   (2 * BK * PADR * 4)
#define OFF_BS  SZ_AB
#define OFF_C2  (2 * SZ_AB)
#define SMEM_GEMM (OFF_C2 + 32 * 256 * 8)      // 99328 B

__global__ void __launch_bounds__(256, 2) gemm_cur1_kernel(
    const float* __restrict__ X, const float* __restrict__ W1,
    const float* __restrict__ b1, int m_base)
{
    extern __shared__ char dsm[];
    float (*As)[BK][PADR] = (float (*)[BK][PADR])(dsm);
    float (*Bs)[BK][PADR] = (float (*)[BK][PADR])(dsm + OFF_BS);
    u64 (*c2s)[256]       = (u64 (*)[256])(dsm + OFF_C2);

    const int tid = threadIdx.x;
    const int tx = tid & 15;
    const int ty = tid >> 4;
    const int m0 = m_base + blockIdx.y * BM;
    const int n0 = blockIdx.x * BN;

    const int lrow = tid >> 1;
    const int lcol = (tid & 1) * 8;

    const float* Aptr = X  + (size_t)(m0 + lrow) * NIN + lcol;
    const float* Bptr = W1 + (size_t)(n0 + lrow) * NIN + lcol;
    const bool bvalid = (n0 + lrow) < NHID;

    u64 pa2[4][8];

    {
        float4 a0 = *(const float4*)(Aptr);
        float4 a1 = *(const float4*)(Aptr + 4);
        float4 bv0 = make_float4(0, 0, 0, 0), bv1 = make_float4(0, 0, 0, 0);
        if (bvalid) { bv0 = *(const float4*)(Bptr); bv1 = *(const float4*)(Bptr + 4); }
        const float a[8]  = {a0.x, a0.y, a0.z, a0.w, a1.x, a1.y, a1.z, a1.w};
        const float bb[8] = {bv0.x, bv0.y, bv0.z, bv0.w, bv1.x, bv1.y, bv1.z, bv1.w};
#pragma unroll
        for (int q = 0; q < 8; ++q) {
            As[0][lcol + q][lrow] = a[q];
            Bs[0][lcol + q][lrow] = bb[q];
        }
    }
    __syncthreads();

    int buf = 0;
#pragma unroll 1
    for (int it = 0; it < NITER; ++it) {
        if (it == 0 || it == 20 || it == 40) {
#pragma unroll
            for (int i = 0; i < 4; ++i)
#pragma unroll
                for (int j = 0; j < 8; ++j) pa2[i][j] = 0ull;
        }

        const bool notlast = (it < NITER - 1);
        float4 na0 = make_float4(0, 0, 0, 0), na1 = na0, nb0 = na0, nb1 = na0;
        if (notlast) {
            na0 = *(const float4*)(Aptr + (it + 1) * BK);
            na1 = *(const float4*)(Aptr + (it + 1) * BK + 4);
            if (bvalid) {
                nb0 = *(const float4*)(Bptr + (it + 1) * BK);
                nb1 = *(const float4*)(Bptr + (it + 1) * BK + 4);
            }
        }

#pragma unroll
        for (int k = 0; k < BK; ++k) {
            u64 a2[4];
            {
                const float4 v0 = *(const float4*)(&As[buf][k][ty * 8]);
                const float4 v1 = *(const float4*)(&As[buf][k][ty * 8 + 4]);
                a2[0] = *(const u64*)&v0.x;
                a2[1] = *(const u64*)&v0.z;
                a2[2] = *(const u64*)&v1.x;
                a2[3] = *(const u64*)&v1.z;
            }
            u64 bd[8];
            {
                const float4 v0 = *(const float4*)(&Bs[buf][k][tx * 8]);
                const float4 v1 = *(const float4*)(&Bs[buf][k][tx * 8 + 4]);
                bd[0] = dup2(v0.x); bd[1] = dup2(v0.y);
                bd[2] = dup2(v0.z); bd[3] = dup2(v0.w);
                bd[4] = dup2(v1.x); bd[5] = dup2(v1.y);
                bd[6] = dup2(v1.z); bd[7] = dup2(v1.w);
            }
#pragma unroll
            for (int i = 0; i < 4; ++i)
#pragma unroll
                for (int j = 0; j < 8; ++j)
                    pa2[i][j] = fma2(a2[i], bd[j], pa2[i][j]);
        }

        if (it == 19) {
#pragma unroll
            for (int i = 0; i < 4; ++i)
#pragma unroll
                for (int j = 0; j < 8; ++j) c2s[i * 8 + j][tid] = pa2[i][j];
        } else if (it == 39 || it == NITER - 1) {
#pragma unroll
            for (int i = 0; i < 4; ++i)
#pragma unroll
                for (int j = 0; j < 8; ++j)
                    c2s[i * 8 + j][tid] = add2(c2s[i * 8 + j][tid], pa2[i][j]);
        }

        if (notlast) {
            const int nb = buf ^ 1;
            const float a[8]  = {na0.x, na0.y, na0.z, na0.w, na1.x, na1.y, na1.z, na1.w};
            const float bb[8] = {nb0.x, nb0.y, nb0.z, nb0.w, nb1.x, nb1.y, nb1.z, nb1.w};
#pragma unroll
            for (int q = 0; q < 8; ++q) {
                As[nb][lcol + q][lrow] = a[q];
                Bs[nb][lcol + q][lrow] = bb[q];
            }
            __syncthreads();
            buf = nb;
        }
    }

#pragma unroll
    for (int i = 0; i < 4; ++i) {
        const size_t row0 = (size_t)(m0 + ty * 8 + 2 * i) * NHID;
        const size_t row1 = row0 + NHID;
#pragma unroll
        for (int j = 0; j < 8; ++j) {
            const int n = n0 + tx * 8 + j;
            if (n < NHID) {
                float lo, hi;
                unpack2(c2s[i * 8 + j][tid], lo, hi);
                const float bb = b1[n];
                g_cur1[row0 + n] = __fadd_rn(lo, bb);
                g_cur1[row1 + n] = __fadd_rn(hi, bb);
            }
        }
    }
}

// ---------------------------------------------------------------------------
// Kernel B (bitwise-validated): chunked LIF recurrence, now with variable tc.
// ---------------------------------------------------------------------------
#define W2P 1001

__global__ void __launch_bounds__(128) lif_chunk_kernel(
    const float* __restrict__ W2, const float* __restrict__ b2,
    float* __restrict__ out, int t0, int tc)
{
    const int b    = blockIdx.x;
    const int tid  = threadIdx.x;
    const int warp = tid >> 5, lane = tid & 31;

    __shared__ float    W2s[NOUT * W2P];
    __shared__ uint32_t masks[2][32];
    __shared__ uint16_t list[2][1024];

    for (int i = tid; i < NOUT * NHID; i += 128) {
        const int o = i / NHID, h = i - o * NHID;
        W2s[o * W2P + h] = W2[i];
    }

    float mem1[8];
    uint32_t rstb;
    float mem2 = 0.f, rst2 = 0.f, b2v = 0.f;

    if (t0 == 0) {
#pragma unroll
        for (int i = 0; i < 8; ++i) mem1[i] = 0.f;
        rstb = 0;
    } else {
#pragma unroll
        for (int i = 0; i < 8; ++i) mem1[i] = g_mem1s[b][i * 128 + tid];
        rstb = g_rst1s[b][tid];
        if (warp == 0 && lane < NOUT) {
            mem2 = g_mem2s[b][lane];
            rst2 = g_rst2s[b][lane];
        }
    }
    if (tid < NOUT) b2v = b2[tid];

    const float* cr0 = g_cur1 + (size_t)b * NHID;
    const size_t tstride = (size_t)BB * NHID;

    float cv[8];
#pragma unroll
    for (int i = 0; i < 8; ++i) {
        const int h = i * 128 + tid;
        cv[i] = (h < NHID) ? __ldg(cr0 + (size_t)t0 * tstride + h) : 0.f;
    }
    __syncthreads();

    int par = 0;
    for (int t = t0; t < t0 + tc; ++t) {
        uint32_t nrst = 0;
#pragma unroll
        for (int i = 0; i < 8; ++i) {
            const int h = i * 128 + tid;
            const float rstv = ((rstb >> i) & 1u) ? 1.f : 0.f;
            const float m = __fsub_rn(__fadd_rn(__fmul_rn(0.9f, mem1[i]), cv[i]), rstv);
            mem1[i] = m;
            const bool s = (m > 1.0f) && (h < NHID);
            const uint32_t bal = __ballot_sync(0xffffffffu, s);
            if (lane == 0) masks[par][i * 4 + warp] = bal;
            if (s) nrst |= (1u << i);
        }
        rstb = nrst;

        float nvv[8];
#pragma unroll
        for (int i = 0; i < 8; ++i) nvv[i] = 0.f;
        if (t + 1 < t0 + tc) {
            const float* crn = cr0 + (size_t)(t + 1) * tstride;
#pragma unroll
            for (int i = 0; i < 8; ++i) {
                const int h = i * 128 + tid;
                if (h < NHID) nvv[i] = __ldg(crn + h);
            }
        }
        __syncthreads();

        if (warp == 0) {
            const uint32_t mw = masks[par][lane];
            const int cnt = __popc(mw);
            int inc = cnt;
#pragma unroll
            for (int d = 1; d < 32; d <<= 1) {
                const int v = __shfl_up_sync(0xffffffffu, inc, d);
                if (lane >= d) inc += v;
            }
            const int excl = inc - cnt;
            const int tot = __shfl_sync(0xffffffffu, inc, 31);
            const int p1  = __shfl_sync(0xffffffffu, excl, 10);
            const int p2  = __shfl_sync(0xffffffffu, excl, 20);
            {
                uint32_t m2w = mw;
                int o = excl;
                const int base = lane * 32;
                while (m2w) {
                    const int bi = __ffs(m2w) - 1;
                    list[par][o++] = (uint16_t)(base + bi);
                    m2w &= m2w - 1;
                }
            }
            __syncwarp();

            const int p = (lane >= 20) ? 2 : ((lane >= 10) ? 1 : 0);
            const int o = lane - p * 10;
            float pacc = 0.f;
            if (lane < 30) {
                const int s0 = (p == 0) ? 0  : ((p == 1) ? p1 : p2);
                const int e0 = (p == 0) ? p1 : ((p == 1) ? p2 : tot);
                const float* wrow = &W2s[o * W2P];
                const uint16_t* L = list[par];
#pragma unroll 4
                for (int ii = s0; ii < e0; ++ii)
                    pacc = __fadd_rn(pacc, wrow[L[ii]]);
            }
            const float v1 = __shfl_sync(0xffffffffu, pacc, (lane + 10) & 31);
            const float v2 = __shfl_sync(0xffffffffu, pacc, (lane + 20) & 31);

            if (lane < NOUT) {
                const float acc = __fadd_rn(__fadd_rn(pacc, v1), v2);
                const float c2v = __fadd_rn(acc, b2v);
                const float m2 = __fsub_rn(__fadd_rn(__fmul_rn(0.9f, mem2), c2v), rst2);
                const float s2 = (m2 > 1.0f) ? 1.0f : 0.0f;
                mem2 = m2;
                rst2 = s2;
                const size_t idx = ((size_t)t * BB + b) * NOUT + lane;
                out[idx] = s2;
                out[(size_t)TT * BB * NOUT + idx] = m2;
            }
        }

        par ^= 1;
#pragma unroll
        for (int i = 0; i < 8; ++i) cv[i] = nvv[i];
    }

#pragma unroll
    for (int i = 0; i < 8; ++i) g_mem1s[b][i * 128 + tid] = mem1[i];
    g_rst1s[b][tid] = rstb;
    if (warp == 0 && lane < NOUT) {
        g_mem2s[b][lane] = mem2;
        g_rst2s[b][lane] = rst2;
    }
}

// ---------------------------------------------------------------------------
extern "C" void kernel_launch(void* const* d_in, const int* in_sizes, int n_in,
                              void* d_out, int out_size)
{
    const float* x  = (const float*)d_in[0];
    const float* W1 = (const float*)d_in[1];
    const float* b1 = (const float*)d_in[2];
    const float* W2 = (const float*)d_in[3];
    const float* b2 = (const float*)d_in[4];
    float* out = (float*)d_out;

    static const int T0s[NCHUNK] = {0, 32, 64, 96};
    static const int TCs[NCHUNK] = {32, 32, 32, 4};

    static cudaStream_t s2 = nullptr;
    static cudaEvent_t evJoin, evG[NCHUNK];
    if (s2 == nullptr) {   // one-time setup; correctness run precedes capture
        cudaStreamCreateWithFlags(&s2, cudaStreamNonBlocking);
        cudaEventCreateWithFlags(&evJoin, cudaEventDisableTiming);
        for (int c = 0; c < NCHUNK; ++c)
            cudaEventCreateWithFlags(&evG[c], cudaEventDisableTiming);
        cudaFuncSetAttribute(gemm_cur1_kernel,
                             cudaFuncAttributeMaxDynamicSharedMemorySize,
                             SMEM_GEMM);
    }

    // Eager gemm enqueue: order = g0, g1, l0, g2, l1, g3, l2, l3
    {
        dim3 g0(8, TCs[0] * 8);
        gemm_cur1_kernel<<<g0, 256, SMEM_GEMM>>>(x, W1, b1, T0s[0] * BB);
        cudaEventRecord(evG[0], 0);
    }
    for (int c = 0; c < NCHUNK; ++c) {
        if (c + 1 < NCHUNK) {
            dim3 g(8, TCs[c + 1] * 8);
            gemm_cur1_kernel<<<g, 256, SMEM_GEMM>>>(x, W1, b1, T0s[c + 1] * BB);
            cudaEventRecord(evG[c + 1], 0);
        }
        cudaStreamWaitEvent(s2, evG[c], 0);
        lif_chunk_kernel<<<BB, 128, 0, s2>>>(W2, b2, out, T0s[c], TCs[c]);
    }

    cudaEventRecord(evJoin, s2);
    cudaStreamWaitEvent(0, evJoin, 0);
}

// round 15
// speedup vs baseline: 1.4615x; 1.1260x over previous
#include <cuda_runtime.h>
#include <cstdint>

#define TT 100
#define BB 1024
#define NIN 784
#define NHID 1000
#define NOUT 10

#define KC 320             // Eigen gebp k-panel (validated R5)
#define NCHUNK 4

__device__ float g_cur1[(size_t)TT * BB * NHID];
__device__ float    g_mem1s[BB][1024];
__device__ uint32_t g_rst1s[BB][128];
__device__ float    g_mem2s[BB][NOUT];
__device__ float    g_rst2s[BB][NOUT];

typedef unsigned long long u64;

__device__ __forceinline__ u64 fma2(u64 a, u64 b, u64 c) {
    u64 d;
    asm("fma.rn.f32x2 %0, %1, %2, %3;" : "=l"(d) : "l"(a), "l"(b), "l"(c));
    return d;
}
__device__ __forceinline__ u64 add2(u64 a, u64 b) {
    u64 d;
    asm("add.rn.f32x2 %0, %1, %2;" : "=l"(d) : "l"(a), "l"(b));
    return d;
}
__device__ __forceinline__ u64 dup2(float x) {
    u64 r;
    asm("mov.b64 %0, {%1,%1};" : "=l"(r) : "f"(x));
    return r;
}
__device__ __forceinline__ void unpack2(u64 v, float& x, float& y) {
    asm("mov.b64 {%0,%1}, %2;" : "=f"(x), "=f"(y) : "l"(v));
}

// ---------------------------------------------------------------------------
// Kernel A: 128 threads/CTA, per-thread microtile 16m x 8n.
// Per thread-k: 6 LDS.128 -> 64 FFMA2 (LDS no longer the binding pipe).
// kc=320 chain association; committed sums in smem; 2 CTAs/SM.
// ---------------------------------------------------------------------------
#define BM 128
#define BN 128
#define BK 16
#define PADR 132
#define NITER (NIN / BK)      // 49; panel commits after it 19, 39, 48

#define SZ_AB   (2 * BK * PADR * 4)            // 16896 B each (double-buffered)
#define OFF_BS  SZ_AB
#define OFF_C2  (2 * SZ_AB)                    // 33792
#define SMEM_GEMM (OFF_C2 + 64 * 128 * 8)      // + 65536 = 99328 B

__global__ void __launch_bounds__(128, 2) gemm_cur1_kernel(
    const float* __restrict__ X, const float* __restrict__ W1,
    const float* __restrict__ b1, int m_base)
{
    extern __shared__ char dsm[];
    float (*As)[BK][PADR] = (float (*)[BK][PADR])(dsm);
    float (*Bs)[BK][PADR] = (float (*)[BK][PADR])(dsm + OFF_BS);
    u64 (*c2s)[128]       = (u64 (*)[128])(dsm + OFF_C2);

    const int tid = threadIdx.x;          // 0..127
    const int tx = tid & 15;              // n-group: 8 cols
    const int ty = tid >> 4;              // m-group: 16 rows (0..7)
    const int m0 = m_base + blockIdx.y * BM;
    const int n0 = blockIdx.x * BN;

    // loader: thread tid owns row tid of both tiles (16 k-floats per slab)
    const float* Aptr = X  + (size_t)(m0 + tid) * NIN;
    const float* Bptr = W1 + (size_t)(n0 + tid) * NIN;
    const bool bvalid = (n0 + tid) < NHID;

    u64 pa2[8][8];   // (C[ty*16+2i], C[ty*16+2i+1]) x n-col j

    // prologue: stage 0
    {
        float4 a[4], bv[4];
#pragma unroll
        for (int q = 0; q < 4; ++q) {
            a[q] = *(const float4*)(Aptr + 4 * q);
            bv[q] = bvalid ? *(const float4*)(Bptr + 4 * q)
                           : make_float4(0, 0, 0, 0);
        }
#pragma unroll
        for (int q = 0; q < 4; ++q) {
            As[0][4 * q + 0][tid] = a[q].x;  As[0][4 * q + 1][tid] = a[q].y;
            As[0][4 * q + 2][tid] = a[q].z;  As[0][4 * q + 3][tid] = a[q].w;
            Bs[0][4 * q + 0][tid] = bv[q].x; Bs[0][4 * q + 1][tid] = bv[q].y;
            Bs[0][4 * q + 2][tid] = bv[q].z; Bs[0][4 * q + 3][tid] = bv[q].w;
        }
    }
    __syncthreads();

    int buf = 0;
#pragma unroll 1
    for (int it = 0; it < NITER; ++it) {
        if (it == 0 || it == 20 || it == 40) {
#pragma unroll
            for (int i = 0; i < 8; ++i)
#pragma unroll
                for (int j = 0; j < 8; ++j) pa2[i][j] = 0ull;
        }

        const bool notlast = (it < NITER - 1);
        float4 na[4], nb[4];
#pragma unroll
        for (int q = 0; q < 4; ++q) { na[q] = make_float4(0,0,0,0); nb[q] = na[q]; }
        if (notlast) {
#pragma unroll
            for (int q = 0; q < 4; ++q) {
                na[q] = *(const float4*)(Aptr + (it + 1) * BK + 4 * q);
                if (bvalid) nb[q] = *(const float4*)(Bptr + (it + 1) * BK + 4 * q);
            }
        }

#pragma unroll
        for (int k = 0; k < BK; ++k) {
            u64 a2[8];
            {
                const float4 v0 = *(const float4*)(&As[buf][k][ty * 16]);
                const float4 v1 = *(const float4*)(&As[buf][k][ty * 16 + 4]);
                const float4 v2 = *(const float4*)(&As[buf][k][ty * 16 + 8]);
                const float4 v3 = *(const float4*)(&As[buf][k][ty * 16 + 12]);
                a2[0] = *(const u64*)&v0.x; a2[1] = *(const u64*)&v0.z;
                a2[2] = *(const u64*)&v1.x; a2[3] = *(const u64*)&v1.z;
                a2[4] = *(const u64*)&v2.x; a2[5] = *(const u64*)&v2.z;
                a2[6] = *(const u64*)&v3.x; a2[7] = *(const u64*)&v3.z;
            }
            u64 bd[8];
            {
                const float4 v0 = *(const float4*)(&Bs[buf][k][tx * 8]);
                const float4 v1 = *(const float4*)(&Bs[buf][k][tx * 8 + 4]);
                bd[0] = dup2(v0.x); bd[1] = dup2(v0.y);
                bd[2] = dup2(v0.z); bd[3] = dup2(v0.w);
                bd[4] = dup2(v1.x); bd[5] = dup2(v1.y);
                bd[6] = dup2(v1.z); bd[7] = dup2(v1.w);
            }
#pragma unroll
            for (int i = 0; i < 8; ++i)
#pragma unroll
                for (int j = 0; j < 8; ++j)
                    pa2[i][j] = fma2(a2[i], bd[j], pa2[i][j]);
        }

        // Eigen panel commits (C += panel), committed value held in smem
        if (it == 19) {
#pragma unroll
            for (int i = 0; i < 8; ++i)
#pragma unroll
                for (int j = 0; j < 8; ++j) c2s[i * 8 + j][tid] = pa2[i][j];
        } else if (it == 39 || it == NITER - 1) {
#pragma unroll
            for (int i = 0; i < 8; ++i)
#pragma unroll
                for (int j = 0; j < 8; ++j)
                    c2s[i * 8 + j][tid] = add2(c2s[i * 8 + j][tid], pa2[i][j]);
        }

        if (notlast) {
            const int nb2 = buf ^ 1;
#pragma unroll
            for (int q = 0; q < 4; ++q) {
                As[nb2][4 * q + 0][tid] = na[q].x;  As[nb2][4 * q + 1][tid] = na[q].y;
                As[nb2][4 * q + 2][tid] = na[q].z;  As[nb2][4 * q + 3][tid] = na[q].w;
                Bs[nb2][4 * q + 0][tid] = nb[q].x;  Bs[nb2][4 * q + 1][tid] = nb[q].y;
                Bs[nb2][4 * q + 2][tid] = nb[q].z;  Bs[nb2][4 * q + 3][tid] = nb[q].w;
            }
            __syncthreads();
            buf = nb2;
        }
    }

#pragma unroll
    for (int i = 0; i < 8; ++i) {
        const size_t row0 = (size_t)(m0 + ty * 16 + 2 * i) * NHID;
        const size_t row1 = row0 + NHID;
#pragma unroll
        for (int j = 0; j < 8; ++j) {
            const int n = n0 + tx * 8 + j;
            if (n < NHID) {
                float lo, hi;
                unpack2(c2s[i * 8 + j][tid], lo, hi);
                const float bb = b1[n];
                g_cur1[row0 + n] = __fadd_rn(lo, bb);
                g_cur1[row1 + n] = __fadd_rn(hi, bb);
            }
        }
    }
}

// ---------------------------------------------------------------------------
// Kernel B (bitwise-validated): chunked LIF recurrence.
// ---------------------------------------------------------------------------
#define W2P 1001

__global__ void __launch_bounds__(128) lif_chunk_kernel(
    const float* __restrict__ W2, const float* __restrict__ b2,
    float* __restrict__ out, int t0, int tc)
{
    const int b    = blockIdx.x;
    const int tid  = threadIdx.x;
    const int warp = tid >> 5, lane = tid & 31;

    __shared__ float    W2s[NOUT * W2P];
    __shared__ uint32_t masks[2][32];
    __shared__ uint16_t list[2][1024];

    for (int i = tid; i < NOUT * NHID; i += 128) {
        const int o = i / NHID, h = i - o * NHID;
        W2s[o * W2P + h] = W2[i];
    }

    float mem1[8];
    uint32_t rstb;
    float mem2 = 0.f, rst2 = 0.f, b2v = 0.f;

    if (t0 == 0) {
#pragma unroll
        for (int i = 0; i < 8; ++i) mem1[i] = 0.f;
        rstb = 0;
    } else {
#pragma unroll
        for (int i = 0; i < 8; ++i) mem1[i] = g_mem1s[b][i * 128 + tid];
        rstb = g_rst1s[b][tid];
        if (warp == 0 && lane < NOUT) {
            mem2 = g_mem2s[b][lane];
            rst2 = g_rst2s[b][lane];
        }
    }
    if (tid < NOUT) b2v = b2[tid];

    const float* cr0 = g_cur1 + (size_t)b * NHID;
    const size_t tstride = (size_t)BB * NHID;

    float cv[8];
#pragma unroll
    for (int i = 0; i < 8; ++i) {
        const int h = i * 128 + tid;
        cv[i] = (h < NHID) ? __ldg(cr0 + (size_t)t0 * tstride + h) : 0.f;
    }
    __syncthreads();

    int par = 0;
    for (int t = t0; t < t0 + tc; ++t) {
        uint32_t nrst = 0;
#pragma unroll
        for (int i = 0; i < 8; ++i) {
            const int h = i * 128 + tid;
            const float rstv = ((rstb >> i) & 1u) ? 1.f : 0.f;
            const float m = __fsub_rn(__fadd_rn(__fmul_rn(0.9f, mem1[i]), cv[i]), rstv);
            mem1[i] = m;
            const bool s = (m > 1.0f) && (h < NHID);
            const uint32_t bal = __ballot_sync(0xffffffffu, s);
            if (lane == 0) masks[par][i * 4 + warp] = bal;
            if (s) nrst |= (1u << i);
        }
        rstb = nrst;

        float nvv[8];
#pragma unroll
        for (int i = 0; i < 8; ++i) nvv[i] = 0.f;
        if (t + 1 < t0 + tc) {
            const float* crn = cr0 + (size_t)(t + 1) * tstride;
#pragma unroll
            for (int i = 0; i < 8; ++i) {
                const int h = i * 128 + tid;
                if (h < NHID) nvv[i] = __ldg(crn + h);
            }
        }
        __syncthreads();

        if (warp == 0) {
            const uint32_t mw = masks[par][lane];
            const int cnt = __popc(mw);
            int inc = cnt;
#pragma unroll
            for (int d = 1; d < 32; d <<= 1) {
                const int v = __shfl_up_sync(0xffffffffu, inc, d);
                if (lane >= d) inc += v;
            }
            const int excl = inc - cnt;
            const int tot = __shfl_sync(0xffffffffu, inc, 31);
            const int p1  = __shfl_sync(0xffffffffu, excl, 10);
            const int p2  = __shfl_sync(0xffffffffu, excl, 20);
            {
                uint32_t m2w = mw;
                int o = excl;
                const int base = lane * 32;
                while (m2w) {
                    const int bi = __ffs(m2w) - 1;
                    list[par][o++] = (uint16_t)(base + bi);
                    m2w &= m2w - 1;
                }
            }
            __syncwarp();

            const int p = (lane >= 20) ? 2 : ((lane >= 10) ? 1 : 0);
            const int o = lane - p * 10;
            float pacc = 0.f;
            if (lane < 30) {
                const int s0 = (p == 0) ? 0  : ((p == 1) ? p1 : p2);
                const int e0 = (p == 0) ? p1 : ((p == 1) ? p2 : tot);
                const float* wrow = &W2s[o * W2P];
                const uint16_t* L = list[par];
#pragma unroll 4
                for (int ii = s0; ii < e0; ++ii)
                    pacc = __fadd_rn(pacc, wrow[L[ii]]);
            }
            const float v1 = __shfl_sync(0xffffffffu, pacc, (lane + 10) & 31);
            const float v2 = __shfl_sync(0xffffffffu, pacc, (lane + 20) & 31);

            if (lane < NOUT) {
                const float acc = __fadd_rn(__fadd_rn(pacc, v1), v2);
                const float c2v = __fadd_rn(acc, b2v);
                const float m2 = __fsub_rn(__fadd_rn(__fmul_rn(0.9f, mem2), c2v), rst2);
                const float s2 = (m2 > 1.0f) ? 1.0f : 0.0f;
                mem2 = m2;
                rst2 = s2;
                const size_t idx = ((size_t)t * BB + b) * NOUT + lane;
                out[idx] = s2;
                out[(size_t)TT * BB * NOUT + idx] = m2;
            }
        }

        par ^= 1;
#pragma unroll
        for (int i = 0; i < 8; ++i) cv[i] = nvv[i];
    }

#pragma unroll
    for (int i = 0; i < 8; ++i) g_mem1s[b][i * 128 + tid] = mem1[i];
    g_rst1s[b][tid] = rstb;
    if (warp == 0 && lane < NOUT) {
        g_mem2s[b][lane] = mem2;
        g_rst2s[b][lane] = rst2;
    }
}

// ---------------------------------------------------------------------------
extern "C" void kernel_launch(void* const* d_in, const int* in_sizes, int n_in,
                              void* d_out, int out_size)
{
    const float* x  = (const float*)d_in[0];
    const float* W1 = (const float*)d_in[1];
    const float* b1 = (const float*)d_in[2];
    const float* W2 = (const float*)d_in[3];
    const float* b2 = (const float*)d_in[4];
    float* out = (float*)d_out;

    static const int T0s[NCHUNK] = {0, 32, 64, 96};
    static const int TCs[NCHUNK] = {32, 32, 32, 4};

    static cudaStream_t s2 = nullptr;
    static cudaEvent_t evJoin, evG[NCHUNK];
    if (s2 == nullptr) {
        cudaStreamCreateWithFlags(&s2, cudaStreamNonBlocking);
        cudaEventCreateWithFlags(&evJoin, cudaEventDisableTiming);
        for (int c = 0; c < NCHUNK; ++c)
            cudaEventCreateWithFlags(&evG[c], cudaEventDisableTiming);
        cudaFuncSetAttribute(gemm_cur1_kernel,
                             cudaFuncAttributeMaxDynamicSharedMemorySize,
                             SMEM_GEMM);
    }

    // Eager gemm enqueue: order = g0, g1, l0, g2, l1, g3, l2, l3
    {
        dim3 g0(8, TCs[0] * 8);
        gemm_cur1_kernel<<<g0, 128, SMEM_GEMM>>>(x, W1, b1, T0s[0] * BB);
        cudaEventRecord(evG[0], 0);
    }
    for (int c = 0; c < NCHUNK; ++c) {
        if (c + 1 < NCHUNK) {
            dim3 g(8, TCs[c + 1] * 8);
            gemm_cur1_kernel<<<g, 128, SMEM_GEMM>>>(x, W1, b1, T0s[c + 1] * BB);
            cudaEventRecord(evG[c + 1], 0);
        }
        cudaStreamWaitEvent(s2, evG[c], 0);
        lif_chunk_kernel<<<BB, 128, 0, s2>>>(W2, b2, out, T0s[c], TCs[c]);
    }

    cudaEventRecord(evJoin, s2);
    cudaStreamWaitEvent(0, evJoin, 0);
}

// round 17
// speedup vs baseline: 1.6173x; 1.1066x over previous
#include <cuda_runtime.h>
#include <cstdint>

#define TT 100
#define BB 1024
#define NIN 784
#define NHID 1000
#define NOUT 10

#define KC 320             // Eigen gebp k-panel (validated R5)
#define NCHUNK 3

__device__ float g_cur1[(size_t)TT * BB * NHID];
__device__ float    g_mem1s[BB][1024];
__device__ uint32_t g_rst1s[BB][128];
__device__ float    g_mem2s[BB][NOUT];
__device__ float    g_rst2s[BB][NOUT];

typedef unsigned long long u64;

__device__ __forceinline__ u64 fma2(u64 a, u64 b, u64 c) {
    u64 d;
    asm("fma.rn.f32x2 %0, %1, %2, %3;" : "=l"(d) : "l"(a), "l"(b), "l"(c));
    return d;
}
__device__ __forceinline__ u64 add2(u64 a, u64 b) {
    u64 d;
    asm("add.rn.f32x2 %0, %1, %2;" : "=l"(d) : "l"(a), "l"(b));
    return d;
}
__device__ __forceinline__ u64 dup2(float x) {
    u64 r;
    asm("mov.b64 %0, {%1,%1};" : "=l"(r) : "f"(x));
    return r;
}
__device__ __forceinline__ void unpack2(u64 v, float& x, float& y) {
    asm("mov.b64 {%0,%1}, %2;" : "=f"(x), "=f"(y) : "l"(v));
}

// B-tile bank swizzle on 16B chunks c in 0..31: scc(c) = c ^ (c >> 3).
// XORs bits 0-1 with bits 3-4 only; bits 3-4 preserved -> bijective.
// Even-chunk loads (and odd-chunk loads) each cover all 8 bank groups
// exactly 2x (= 512B wavefront minimum); warp STS octets stay conflict-free.
__device__ __forceinline__ int scc(int c) { return c ^ (c >> 3); }

// ---------------------------------------------------------------------------
// Kernel A: 128 threads/CTA, 16m x 8n per-thread microtile, FFMA2, committed
// sums in smem, kc=320 chain association, swizzled B tile.
// ---------------------------------------------------------------------------
#define BM 128
#define BN 128
#define BK 16
#define PADA 132                      // A row stride (floats)
#define NITER (NIN / BK)              // 49; panel commits after it 19, 39, 48

#define SZ_A    (2 * BK * PADA * 4)   // 16896 B
#define SZ_B    (2 * BK * 128 * 4)    // 16384 B
#define OFF_BS  SZ_A
#define OFF_C2  (SZ_A + SZ_B)         // 33280
#define SMEM_GEMM (OFF_C2 + 64 * 128 * 8)   // + 65536 = 98816 B

__global__ void __launch_bounds__(128, 2) gemm_cur1_kernel(
    const float* __restrict__ X, const float* __restrict__ W1,
    const float* __restrict__ b1, int m_base)
{
    extern __shared__ char dsm[];
    float (*As)[BK][PADA] = (float (*)[BK][PADA])(dsm);
    float (*Bs)[BK][128]  = (float (*)[BK][128])(dsm + OFF_BS);
    u64 (*c2s)[128]       = (u64 (*)[128])(dsm + OFF_C2);

    const int tid = threadIdx.x;          // 0..127
    const int tx = tid & 15;              // n-group: 8 cols
    const int ty = tid >> 4;              // m-group: 16 rows
    const int m0 = m_base + blockIdx.y * BM;
    const int n0 = blockIdx.x * BN;

    // swizzled B columns
    const int bcol = (scc(tid >> 2) << 2) | (tid & 3);   // store column
    const int bc0  = scc(2 * tx) << 2;                   // load chunk cols
    const int bc1  = scc(2 * tx + 1) << 2;

    const float* Aptr = X  + (size_t)(m0 + tid) * NIN;
    const float* Bptr = W1 + (size_t)(n0 + tid) * NIN;
    const bool bvalid = (n0 + tid) < NHID;

    u64 pa2[8][8];

    // prologue: stage 0
    {
        float4 a[4], bv[4];
#pragma unroll
        for (int q = 0; q < 4; ++q) {
            a[q] = *(const float4*)(Aptr + 4 * q);
            bv[q] = bvalid ? *(const float4*)(Bptr + 4 * q)
                           : make_float4(0, 0, 0, 0);
        }
#pragma unroll
        for (int q = 0; q < 4; ++q) {
            As[0][4 * q + 0][tid] = a[q].x;   As[0][4 * q + 1][tid] = a[q].y;
            As[0][4 * q + 2][tid] = a[q].z;   As[0][4 * q + 3][tid] = a[q].w;
            Bs[0][4 * q + 0][bcol] = bv[q].x; Bs[0][4 * q + 1][bcol] = bv[q].y;
            Bs[0][4 * q + 2][bcol] = bv[q].z; Bs[0][4 * q + 3][bcol] = bv[q].w;
        }
    }
    __syncthreads();

    int buf = 0;
#pragma unroll 1
    for (int it = 0; it < NITER; ++it) {
        if (it == 0 || it == 20 || it == 40) {
#pragma unroll
            for (int i = 0; i < 8; ++i)
#pragma unroll
                for (int j = 0; j < 8; ++j) pa2[i][j] = 0ull;
        }

        const bool notlast = (it < NITER - 1);
        float4 na[4], nb[4];
#pragma unroll
        for (int q = 0; q < 4; ++q) { na[q] = make_float4(0,0,0,0); nb[q] = na[q]; }
        if (notlast) {
#pragma unroll
            for (int q = 0; q < 4; ++q) {
                na[q] = *(const float4*)(Aptr + (it + 1) * BK + 4 * q);
                if (bvalid) nb[q] = *(const float4*)(Bptr + (it + 1) * BK + 4 * q);
            }
        }

#pragma unroll
        for (int k = 0; k < BK; ++k) {
            u64 a2[8];
            {
                const float4 v0 = *(const float4*)(&As[buf][k][ty * 16]);
                const float4 v1 = *(const float4*)(&As[buf][k][ty * 16 + 4]);
                const float4 v2 = *(const float4*)(&As[buf][k][ty * 16 + 8]);
                const float4 v3 = *(const float4*)(&As[buf][k][ty * 16 + 12]);
                a2[0] = *(const u64*)&v0.x; a2[1] = *(const u64*)&v0.z;
                a2[2] = *(const u64*)&v1.x; a2[3] = *(const u64*)&v1.z;
                a2[4] = *(const u64*)&v2.x; a2[5] = *(const u64*)&v2.z;
                a2[6] = *(const u64*)&v3.x; a2[7] = *(const u64*)&v3.z;
            }
            u64 bd[8];
            {
                const float4 v0 = *(const float4*)(&Bs[buf][k][bc0]);
                const float4 v1 = *(const float4*)(&Bs[buf][k][bc1]);
                bd[0] = dup2(v0.x); bd[1] = dup2(v0.y);
                bd[2] = dup2(v0.z); bd[3] = dup2(v0.w);
                bd[4] = dup2(v1.x); bd[5] = dup2(v1.y);
                bd[6] = dup2(v1.z); bd[7] = dup2(v1.w);
            }
#pragma unroll
            for (int i = 0; i < 8; ++i)
#pragma unroll
                for (int j = 0; j < 8; ++j)
                    pa2[i][j] = fma2(a2[i], bd[j], pa2[i][j]);
        }

        // Eigen panel commits (C += panel), committed value held in smem
        if (it == 19) {
#pragma unroll
            for (int i = 0; i < 8; ++i)
#pragma unroll
                for (int j = 0; j < 8; ++j) c2s[i * 8 + j][tid] = pa2[i][j];
        } else if (it == 39 || it == NITER - 1) {
#pragma unroll
            for (int i = 0; i < 8; ++i)
#pragma unroll
                for (int j = 0; j < 8; ++j)
                    c2s[i * 8 + j][tid] = add2(c2s[i * 8 + j][tid], pa2[i][j]);
        }

        if (notlast) {
            const int nb2 = buf ^ 1;
#pragma unroll
            for (int q = 0; q < 4; ++q) {
                As[nb2][4 * q + 0][tid] = na[q].x;   As[nb2][4 * q + 1][tid] = na[q].y;
                As[nb2][4 * q + 2][tid] = na[q].z;   As[nb2][4 * q + 3][tid] = na[q].w;
                Bs[nb2][4 * q + 0][bcol] = nb[q].x;  Bs[nb2][4 * q + 1][bcol] = nb[q].y;
                Bs[nb2][4 * q + 2][bcol] = nb[q].z;  Bs[nb2][4 * q + 3][bcol] = nb[q].w;
            }
            __syncthreads();
            buf = nb2;
        }
    }

#pragma unroll
    for (int i = 0; i < 8; ++i) {
        const size_t row0 = (size_t)(m0 + ty * 16 + 2 * i) * NHID;
        const size_t row1 = row0 + NHID;
#pragma unroll
        for (int j = 0; j < 8; ++j) {
            const int n = n0 + tx * 8 + j;
            if (n < NHID) {
                float lo, hi;
                unpack2(c2s[i * 8 + j][tid], lo, hi);
                const float bb = b1[n];
                g_cur1[row0 + n] = __fadd_rn(lo, bb);
                g_cur1[row1 + n] = __fadd_rn(hi, bb);
            }
        }
    }
}

// ---------------------------------------------------------------------------
// Kernel B (bitwise-validated): chunked LIF recurrence.
// ---------------------------------------------------------------------------
#define W2P 1001

__global__ void __launch_bounds__(128) lif_chunk_kernel(
    const float* __restrict__ W2, const float* __restrict__ b2,
    float* __restrict__ out, int t0, int tc)
{
    const int b    = blockIdx.x;
    const int tid  = threadIdx.x;
    const int warp = tid >> 5, lane = tid & 31;

    __shared__ float    W2s[NOUT * W2P];
    __shared__ uint32_t masks[2][32];
    __shared__ uint16_t list[2][1024];

    for (int i = tid; i < NOUT * NHID; i += 128) {
        const int o = i / NHID, h = i - o * NHID;
        W2s[o * W2P + h] = W2[i];
    }

    float mem1[8];
    uint32_t rstb;
    float mem2 = 0.f, rst2 = 0.f, b2v = 0.f;

    if (t0 == 0) {
#pragma unroll
        for (int i = 0; i < 8; ++i) mem1[i] = 0.f;
        rstb = 0;
    } else {
#pragma unroll
        for (int i = 0; i < 8; ++i) mem1[i] = g_mem1s[b][i * 128 + tid];
        rstb = g_rst1s[b][tid];
        if (warp == 0 && lane < NOUT) {
            mem2 = g_mem2s[b][lane];
            rst2 = g_rst2s[b][lane];
        }
    }
    if (tid < NOUT) b2v = b2[tid];

    const float* cr0 = g_cur1 + (size_t)b * NHID;
    const size_t tstride = (size_t)BB * NHID;

    float cv[8];
#pragma unroll
    for (int i = 0; i < 8; ++i) {
        const int h = i * 128 + tid;
        cv[i] = (h < NHID) ? __ldg(cr0 + (size_t)t0 * tstride + h) : 0.f;
    }
    __syncthreads();

    int par = 0;
    for (int t = t0; t < t0 + tc; ++t) {
        uint32_t nrst = 0;
#pragma unroll
        for (int i = 0; i < 8; ++i) {
            const int h = i * 128 + tid;
            const float rstv = ((rstb >> i) & 1u) ? 1.f : 0.f;
            const float m = __fsub_rn(__fadd_rn(__fmul_rn(0.9f, mem1[i]), cv[i]), rstv);
            mem1[i] = m;
            const bool s = (m > 1.0f) && (h < NHID);
            const uint32_t bal = __ballot_sync(0xffffffffu, s);
            if (lane == 0) masks[par][i * 4 + warp] = bal;
            if (s) nrst |= (1u << i);
        }
        rstb = nrst;

        float nvv[8];
#pragma unroll
        for (int i = 0; i < 8; ++i) nvv[i] = 0.f;
        if (t + 1 < t0 + tc) {
            const float* crn = cr0 + (size_t)(t + 1) * tstride;
#pragma unroll
            for (int i = 0; i < 8; ++i) {
                const int h = i * 128 + tid;
                if (h < NHID) nvv[i] = __ldg(crn + h);
            }
        }
        __syncthreads();

        if (warp == 0) {
            const uint32_t mw = masks[par][lane];
            const int cnt = __popc(mw);
            int inc = cnt;
#pragma unroll
            for (int d = 1; d < 32; d <<= 1) {
                const int v = __shfl_up_sync(0xffffffffu, inc, d);
                if (lane >= d) inc += v;
            }
            const int excl = inc - cnt;
            const int tot = __shfl_sync(0xffffffffu, inc, 31);
            const int p1  = __shfl_sync(0xffffffffu, excl, 10);
            const int p2  = __shfl_sync(0xffffffffu, excl, 20);
            {
                uint32_t m2w = mw;
                int o = excl;
                const int base = lane * 32;
                while (m2w) {
                    const int bi = __ffs(m2w) - 1;
                    list[par][o++] = (uint16_t)(base + bi);
                    m2w &= m2w - 1;
                }
            }
            __syncwarp();

            const int p = (lane >= 20) ? 2 : ((lane >= 10) ? 1 : 0);
            const int o = lane - p * 10;
            float pacc = 0.f;
            if (lane < 30) {
                const int s0 = (p == 0) ? 0  : ((p == 1) ? p1 : p2);
                const int e0 = (p == 0) ? p1 : ((p == 1) ? p2 : tot);
                const float* wrow = &W2s[o * W2P];
                const uint16_t* L = list[par];
#pragma unroll 4
                for (int ii = s0; ii < e0; ++ii)
                    pacc = __fadd_rn(pacc, wrow[L[ii]]);
            }
            const float v1 = __shfl_sync(0xffffffffu, pacc, (lane + 10) & 31);
            const float v2 = __shfl_sync(0xffffffffu, pacc, (lane + 20) & 31);

            if (lane < NOUT) {
                const float acc = __fadd_rn(__fadd_rn(pacc, v1), v2);
                const float c2v = __fadd_rn(acc, b2v);
                const float m2 = __fsub_rn(__fadd_rn(__fmul_rn(0.9f, mem2), c2v), rst2);
                const float s2 = (m2 > 1.0f) ? 1.0f : 0.0f;
                mem2 = m2;
                rst2 = s2;
                const size_t idx = ((size_t)t * BB + b) * NOUT + lane;
                out[idx] = s2;
                out[(size_t)TT * BB * NOUT + idx] = m2;
            }
        }

        par ^= 1;
#pragma unroll
        for (int i = 0; i < 8; ++i) cv[i] = nvv[i];
    }

#pragma unroll
    for (int i = 0; i < 8; ++i) g_mem1s[b][i * 128 + tid] = mem1[i];
    g_rst1s[b][tid] = rstb;
    if (warp == 0 && lane < NOUT) {
        g_mem2s[b][lane] = mem2;
        g_rst2s[b][lane] = rst2;
    }
}

// ---------------------------------------------------------------------------
extern "C" void kernel_launch(void* const* d_in, const int* in_sizes, int n_in,
                              void* d_out, int out_size)
{
    const float* x  = (const float*)d_in[0];
    const float* W1 = (const float*)d_in[1];
    const float* b1 = (const float*)d_in[2];
    const float* W2 = (const float*)d_in[3];
    const float* b2 = (const float*)d_in[4];
    float* out = (float*)d_out;

    static const int T0s[NCHUNK] = {0, 48, 96};
    static const int TCs[NCHUNK] = {48, 48, 4};

    static cudaStream_t s2 = nullptr;
    static cudaEvent_t evJoin, evG[NCHUNK];
    if (s2 == nullptr) {
        cudaStreamCreateWithFlags(&s2, cudaStreamNonBlocking);
        cudaEventCreateWithFlags(&evJoin, cudaEventDisableTiming);
        for (int c = 0; c < NCHUNK; ++c)
            cudaEventCreateWithFlags(&evG[c], cudaEventDisableTiming);
        cudaFuncSetAttribute(gemm_cur1_kernel,
                             cudaFuncAttributeMaxDynamicSharedMemorySize,
                             SMEM_GEMM);
    }

    // Eager gemm enqueue: g0, g1, l0, g2, l1, l2
    {
        dim3 g0(8, TCs[0] * 8);
        gemm_cur1_kernel<<<g0, 128, SMEM_GEMM>>>(x, W1, b1, T0s[0] * BB);
        cudaEventRecord(evG[0], 0);
    }
    for (int c = 0; c < NCHUNK; ++c) {
        if (c + 1 < NCHUNK) {
            dim3 g(8, TCs[c + 1] * 8);
            gemm_cur1_kernel<<<g, 128, SMEM_GEMM>>>(x, W1, b1, T0s[c + 1] * BB);
            cudaEventRecord(evG[c + 1], 0);
        }
        cudaStreamWaitEvent(s2, evG[c], 0);
        lif_chunk_kernel<<<BB, 128, 0, s2>>>(W2, b2, out, T0s[c], TCs[c]);
    }

    cudaEventRecord(evJoin, s2);
    cudaStreamWaitEvent(0, evJoin, 0);
}